// round 10
// baseline (speedup 1.0000x reference)
#include <cuda_runtime.h>
#include <cuda_fp16.h>
#include <cstdint>

#define B_SZ    2048
#define N_IN    512
#define T_STEPS 100
#define H1      512
#define H2      256
#define O_OUT   5
#define M_TOT   (B_SZ * T_STEPS)   // 204800

// ---------------- scratch globals (allocation-free rule) ----------------
__device__ __half g_xh[(size_t)M_TOT * N_IN];   // x transposed, fp16
__device__ __half g_w1h[H1 * N_IN];             // W1 fp16
__device__ __half g_h1[(size_t)M_TOT * H1];     // fp16 h1 for all t
__device__ float  g_w2t[H1 * H2];               // W2 transposed [k][j]

// ---------------- PTX helpers ----------------
__device__ __forceinline__ uint32_t smem_u32(const void* p) {
    uint32_t a;
    asm("{ .reg .u64 t; cvta.to.shared.u64 t, %1; cvt.u32.u64 %0, t; }"
        : "=r"(a) : "l"(p));
    return a;
}
__device__ __forceinline__ void cp_async16(uint32_t dst, const void* src) {
    asm volatile("cp.async.cg.shared.global [%0], [%1], 16;" :: "r"(dst), "l"(src));
}
#define CP_COMMIT() asm volatile("cp.async.commit_group;" ::: "memory")
template <int N>
__device__ __forceinline__ void cp_wait() {
    asm volatile("cp.async.wait_group %0;" :: "n"(N) : "memory");
}
__device__ __forceinline__ void ldsm4(uint32_t* r, uint32_t addr) {
    asm volatile("ldmatrix.sync.aligned.m8n8.x4.shared.b16 {%0,%1,%2,%3}, [%4];"
                 : "=r"(r[0]), "=r"(r[1]), "=r"(r[2]), "=r"(r[3]) : "r"(addr));
}
__device__ __forceinline__ void ldsm4t(uint32_t* r, uint32_t addr) {
    asm volatile("ldmatrix.sync.aligned.m8n8.x4.trans.shared.b16 {%0,%1,%2,%3}, [%4];"
                 : "=r"(r[0]), "=r"(r[1]), "=r"(r[2]), "=r"(r[3]) : "r"(addr));
}
__device__ __forceinline__ void mma16816(float* c, const uint32_t* a, const uint32_t* b) {
    asm volatile("mma.sync.aligned.m16n8k16.row.col.f32.f16.f16.f32 "
                 "{%0,%1,%2,%3},{%4,%5,%6,%7},{%8,%9},{%0,%1,%2,%3};"
                 : "+f"(c[0]), "+f"(c[1]), "+f"(c[2]), "+f"(c[3])
                 : "r"(a[0]), "r"(a[1]), "r"(a[2]), "r"(a[3]), "r"(b[0]), "r"(b[1]));
}

// ---------------------------------------------------------------------------
// Transpose x (B, N, T) -> fp16 xh at [(b*T+t)][n]
// ---------------------------------------------------------------------------
__global__ void transpose_half_x(const float* __restrict__ x,
                                 __half* __restrict__ xh) {
    __shared__ float tile[32][33];
    int b  = blockIdx.z;
    int t0 = blockIdx.x * 32;
    int n0 = blockIdx.y * 32;
    int tx = threadIdx.x, ty = threadIdx.y;   // 32 x 8
#pragma unroll
    for (int i = 0; i < 4; i++) {
        int n = n0 + ty + i * 8;
        int t = t0 + tx;
        if (t < T_STEPS)
            tile[ty + i * 8][tx] = x[((size_t)b * N_IN + n) * T_STEPS + t];
    }
    __syncthreads();
#pragma unroll
    for (int i = 0; i < 4; i++) {
        int t = t0 + ty + i * 8;
        int n = n0 + tx;
        if (t < T_STEPS)
            xh[((size_t)b * T_STEPS + t) * N_IN + n] =
                __float2half_rn(tile[tx][ty + i * 8]);
    }
}

// ---------------------------------------------------------------------------
// Convert W1 to fp16
// ---------------------------------------------------------------------------
__global__ void conv_w1(const float* __restrict__ w, __half* __restrict__ wh) {
    int i = blockIdx.x * 256 + threadIdx.x;
    wh[i] = __float2half_rn(w[i]);
}

// ---------------------------------------------------------------------------
// Transpose W2 (H2, H1) -> (H1, H2)
// ---------------------------------------------------------------------------
__global__ void transpose_w2_kernel(const float* __restrict__ w2,
                                    float* __restrict__ w2t) {
    __shared__ float tile[32][33];
    int k0 = blockIdx.x * 32;
    int j0 = blockIdx.y * 32;
    int tx = threadIdx.x, ty = threadIdx.y;
#pragma unroll
    for (int i = 0; i < 4; i++)
        tile[ty + i * 8][tx] = w2[(size_t)(j0 + ty + i * 8) * H1 + k0 + tx];
    __syncthreads();
#pragma unroll
    for (int i = 0; i < 4; i++)
        w2t[(size_t)(k0 + ty + i * 8) * H2 + j0 + tx] = tile[tx][ty + i * 8];
}

// ---------------------------------------------------------------------------
// GEMM1 via mma.sync fp16, single pass, fp16 output:
//   h1[m][j] = fp16( sum_k x[m][k] * W1[j][k] + b1[j] )
// BM=128, BN=128, BK=64, 3-stage cp.async pipeline, ONE sync per k-chunk,
// 2 CTAs/SM.
// ---------------------------------------------------------------------------
#define BK        64
#define NKC       (N_IN / BK)        // 8
#define ROWB      144                // bytes per padded smem row (64h + 8h pad)
#define MATB      (128 * ROWB)       // 18432 bytes per matrix tile
#define STAGEB    (2 * MATB)         // A, W = 36864
#define NSTAGE    3
#define GEMM_SMEM (NSTAGE * STAGEB)  // 110592

__device__ __forceinline__ void g1_load_stage(uint32_t sbase, int kc,
                                              const __half* xh, const __half* wh,
                                              int m0, int j0, int tid) {
    int kb = kc * BK;
#pragma unroll
    for (int i = 0; i < 2; i++) {
        int c = tid + i * 256;              // 0..511: 128 rows x 4 segs
        int row = c >> 2, seg = c & 3;
        uint32_t d = (uint32_t)(row * ROWB + seg * 16);
        cp_async16(sbase + d,        xh + (size_t)(m0 + row) * N_IN + kb + seg * 8);
        cp_async16(sbase + MATB + d, wh + (size_t)(j0 + row) * N_IN + kb + seg * 8);
    }
    CP_COMMIT();
}

__global__ __launch_bounds__(256, 2) void gemm1_mma_kernel(
    const __half* __restrict__ xh, const __half* __restrict__ wh,
    const float* __restrict__ b1, __half* __restrict__ h1) {
    extern __shared__ char smem[];
    uint32_t sb = smem_u32(smem);
    int tid  = threadIdx.x;
    int wid  = tid >> 5, lane = tid & 31;
    int m0   = blockIdx.y * 128;
    int j0   = blockIdx.x * 128;
    int mbase = (wid & 1) * 64;          // 2 m-groups, warp tile 64 rows
    int nbase = (wid >> 1) * 32;         // 4 n-groups, warp tile 32 cols
    int grp  = lane >> 3, lrow = lane & 7;

    uint32_t aoff = (uint32_t)((mbase + (grp & 1) * 8 + lrow) * ROWB + (grp >> 1) * 16);
    uint32_t boff = (uint32_t)((nbase + (grp >> 1) * 8 + lrow) * ROWB + (grp & 1) * 16);

    float acc[4][4][4];
#pragma unroll
    for (int mt = 0; mt < 4; mt++)
#pragma unroll
        for (int nt = 0; nt < 4; nt++)
#pragma unroll
            for (int q = 0; q < 4; q++) acc[mt][nt][q] = 0.0f;

    // prologue: stages 0, 1
    g1_load_stage(sb,          0, xh, wh, m0, j0, tid);
    g1_load_stage(sb + STAGEB, 1, xh, wh, m0, j0, tid);

#pragma unroll 1
    for (int kc = 0; kc < NKC; kc++) {
        cp_wait<1>();      // stage kc landed (this thread's view)
        __syncthreads();   // publish kc to all + all warps done with kc-1
        if (kc + 2 < NKC)  // slot (kc+2)%3 == (kc-1)%3, freed by the sync above
            g1_load_stage(sb + ((kc + 2) % NSTAGE) * STAGEB, kc + 2,
                          xh, wh, m0, j0, tid);
        else
            CP_COMMIT();   // keep wait_group accounting in step

        uint32_t sA = sb + (kc % NSTAGE) * STAGEB;
        uint32_t sW = sA + MATB;
#pragma unroll
        for (int kk = 0; kk < 4; kk++) {
            uint32_t ah[4][4];
#pragma unroll
            for (int mt = 0; mt < 4; mt++)
                ldsm4(ah[mt], sA + aoff + mt * (16 * ROWB) + kk * 32);
            uint32_t bh[4][2];
#pragma unroll
            for (int nt2 = 0; nt2 < 2; nt2++) {
                uint32_t r[4];
                ldsm4t(r, sW + boff + nt2 * (16 * ROWB) + kk * 32);
                bh[nt2 * 2][0] = r[0]; bh[nt2 * 2][1] = r[1];
                bh[nt2 * 2 + 1][0] = r[2]; bh[nt2 * 2 + 1][1] = r[3];
            }
#pragma unroll
            for (int mt = 0; mt < 4; mt++)
#pragma unroll
                for (int nt = 0; nt < 4; nt++)
                    mma16816(acc[mt][nt], ah[mt], bh[nt]);
        }
    }

    // epilogue: add bias, store fp16
    int r0 = lane >> 2, c0 = (lane & 3) * 2;
#pragma unroll
    for (int nt = 0; nt < 4; nt++) {
        int col = j0 + nbase + nt * 8 + c0;
        float2 bb = *(const float2*)&b1[col];
#pragma unroll
        for (int mt = 0; mt < 4; mt++) {
            int row = m0 + mbase + mt * 16 + r0;
            __half2 v0 = __floats2half2_rn(acc[mt][nt][0] + bb.x, acc[mt][nt][1] + bb.y);
            __half2 v1 = __floats2half2_rn(acc[mt][nt][2] + bb.x, acc[mt][nt][3] + bb.y);
            *(__half2*)&h1[(size_t)row * H1 + col]       = v0;
            *(__half2*)&h1[(size_t)(row + 8) * H1 + col] = v1;
        }
    }
}

// ---------------------------------------------------------------------------
// Phase B: spike-sparse LIF stack. RB=4 rows/block, 512 blocks (~1 wave),
// 256 threads. Warp w: row = w>>1, half = w&1, neurons k = half*256+i*32+lane.
// Double-buffered bitmasks -> 2 barriers/step. uint4 zero-skip word scan.
// ---------------------------------------------------------------------------
#define RB 4
__global__ __launch_bounds__(256) void phase_b_kernel(
    const __half* __restrict__ h1all, const float* __restrict__ w2t,
    const float* __restrict__ b2,    const float* __restrict__ Wo,
    const float* __restrict__ bo,    float* __restrict__ out) {
    __shared__ uint32_t s1bits[2][RB][16];
    __shared__ uint32_t s2bits[2][RB][8];
    __shared__ float    Wos[O_OUT * 256];
    __shared__ float    bos[8];

    int tid  = threadIdx.x;
    int wid  = tid >> 5, lane = tid & 31;
    int b0   = blockIdx.x * RB;
    int row  = wid >> 1;                 // 0..3
    int half = wid & 1;                  // k-half

    for (int i = tid; i < O_OUT * 256; i += 256) Wos[i] = Wo[i];
    if (tid < O_OUT) bos[tid] = bo[tid];

    float v1[8];
#pragma unroll
    for (int i = 0; i < 8; i++) v1[i] = 0.0f;
    float v2[RB];
#pragma unroll
    for (int r = 0; r < RB; r++) v2[r] = 0.0f;
    float b2r = b2[tid];
    float vo = 0.0f, oac = 0.0f;         // LIF3: wid<4 = row, lanes 0..4 = cols

    const __half* hbase = h1all + ((size_t)(b0 + row) * T_STEPS) * H1
                                + half * 256 + lane;
    // prefetch t=0
    __half cur[8], nxt[8];
#pragma unroll
    for (int i = 0; i < 8; i++) cur[i] = hbase[i * 32];
    __syncthreads();

#pragma unroll 1
    for (int t = 0; t < T_STEPS; t++) {
        int buf = t & 1;
        // issue next-t loads early (independent of everything below)
        if (t + 1 < T_STEPS) {
            const __half* hn = hbase + (size_t)(t + 1) * H1;
#pragma unroll
            for (int i = 0; i < 8; i++) nxt[i] = hn[i * 32];
        }

        // ---- LIF1 -> bitmask (word = half*8+i, bit = lane) ----
#pragma unroll
        for (int i = 0; i < 8; i++) {
            float v = v1[i];
            v = v + (__half2float(cur[i]) - v) * 0.5f;
            bool sp = (v >= 1.0f);
            v1[i] = sp ? 0.0f : v;
            uint32_t m = __ballot_sync(0xffffffffu, sp);
            if (lane == 0) s1bits[buf][row][half * 8 + i] = m;
        }
        __syncthreads();

        // ---- sparse GEMM2 + LIF2 (thread = col j = tid) ----
#pragma unroll
        for (int r = 0; r < RB; r++) {
            float acc = b2r;
            const uint4* wq = (const uint4*)s1bits[buf][r];
#pragma unroll
            for (int q = 0; q < 4; q++) {
                uint4 w4 = wq[q];
                if ((w4.x | w4.y | w4.z | w4.w) == 0u) continue;
                uint32_t ws[4] = {w4.x, w4.y, w4.z, w4.w};
#pragma unroll
                for (int c = 0; c < 4; c++) {
                    uint32_t word = ws[c];
                    while (word) {
                        int k = (q * 4 + c) * 32 + (__ffs(word) - 1);
                        word &= word - 1;
                        acc += w2t[(size_t)k * H2 + tid];
                    }
                }
            }
            float v = v2[r];
            v = v + (acc - v) * 0.5f;
            bool sp = (v >= 1.0f);
            v2[r] = sp ? 0.0f : v;
            uint32_t m = __ballot_sync(0xffffffffu, sp);
            if (lane == 0) s2bits[buf][r][wid] = m;
        }
        __syncthreads();

        // ---- sparse GEMM3 + LIF3 (wid<4 = row, lanes 0..4 = outputs) ----
        if (wid < RB && lane < O_OUT) {
            float sum = bos[lane];
#pragma unroll
            for (int w = 0; w < 8; w++) {
                uint32_t word = s2bits[buf][wid][w];
                while (word) {
                    int j = w * 32 + (__ffs(word) - 1);
                    word &= word - 1;
                    sum += Wos[lane * 256 + j];
                }
            }
            float v = vo;
            v = v + (sum - v) * 0.5f;
            bool sp = (v >= 1.0f);
            vo = sp ? 0.0f : v;
            if (sp) oac += 1.0f;
        }
        // no barrier: next step writes the OTHER buffer

#pragma unroll
        for (int i = 0; i < 8; i++) cur[i] = nxt[i];
    }

    if (wid < RB && lane < O_OUT)
        out[(size_t)(b0 + wid) * O_OUT + lane] = oac * (1.0f / T_STEPS);
}

// ---------------------------------------------------------------------------
extern "C" void kernel_launch(void* const* d_in, const int* in_sizes, int n_in,
                              void* d_out, int out_size) {
    const float* x  = (const float*)d_in[0];
    const float* W1 = (const float*)d_in[1];
    const float* b1 = (const float*)d_in[2];
    const float* W2 = (const float*)d_in[3];
    const float* b2 = (const float*)d_in[4];
    const float* Wo = (const float*)d_in[5];
    const float* bo = (const float*)d_in[6];
    float* out = (float*)d_out;

    __half *xh, *wh, *h1;
    float *w2t;
    cudaGetSymbolAddress((void**)&xh,  g_xh);
    cudaGetSymbolAddress((void**)&wh,  g_w1h);
    cudaGetSymbolAddress((void**)&h1,  g_h1);
    cudaGetSymbolAddress((void**)&w2t, g_w2t);

    cudaFuncSetAttribute(gemm1_mma_kernel,
                         cudaFuncAttributeMaxDynamicSharedMemorySize, GEMM_SMEM);

    transpose_half_x<<<dim3(4, 16, B_SZ), dim3(32, 8)>>>(x, xh);
    conv_w1<<<(H1 * N_IN) / 256, 256>>>(W1, wh);
    transpose_w2_kernel<<<dim3(16, 8), dim3(32, 8)>>>(W2, w2t);
    gemm1_mma_kernel<<<dim3(H1 / 128, M_TOT / 128), 256, GEMM_SMEM>>>(
        xh, wh, b1, h1);
    phase_b_kernel<<<B_SZ / RB, 256>>>(h1, w2t, b2, Wo, bo, out);
}

// round 12
// speedup vs baseline: 2.0953x; 2.0953x over previous
#include <cuda_runtime.h>
#include <cuda_fp16.h>
#include <cstdint>

#define B_SZ    2048
#define N_IN    512
#define T_STEPS 100
#define H1      512
#define H2      256
#define O_OUT   5
#define M_TOT   (B_SZ * T_STEPS)   // 204800

// ---------------- scratch globals (allocation-free rule) ----------------
__device__ __half g_xh[(size_t)M_TOT * N_IN];   // x transposed, fp16
__device__ __half g_w1h[H1 * N_IN];             // W1 fp16
__device__ __half g_h1[(size_t)M_TOT * H1];     // fp16 h1 for all t
__device__ float  g_w2t[H1 * H2];               // W2 transposed [k][j]

// ---------------- PTX helpers ----------------
__device__ __forceinline__ uint32_t smem_u32(const void* p) {
    uint32_t a;
    asm("{ .reg .u64 t; cvta.to.shared.u64 t, %1; cvt.u32.u64 %0, t; }"
        : "=r"(a) : "l"(p));
    return a;
}
__device__ __forceinline__ void cp_async16(uint32_t dst, const void* src) {
    asm volatile("cp.async.cg.shared.global [%0], [%1], 16;" :: "r"(dst), "l"(src));
}
#define CP_COMMIT() asm volatile("cp.async.commit_group;" ::: "memory")
template <int N>
__device__ __forceinline__ void cp_wait() {
    asm volatile("cp.async.wait_group %0;" :: "n"(N) : "memory");
}
__device__ __forceinline__ void ldsm4(uint32_t* r, uint32_t addr) {
    asm volatile("ldmatrix.sync.aligned.m8n8.x4.shared.b16 {%0,%1,%2,%3}, [%4];"
                 : "=r"(r[0]), "=r"(r[1]), "=r"(r[2]), "=r"(r[3]) : "r"(addr));
}
__device__ __forceinline__ void ldsm4t(uint32_t* r, uint32_t addr) {
    asm volatile("ldmatrix.sync.aligned.m8n8.x4.trans.shared.b16 {%0,%1,%2,%3}, [%4];"
                 : "=r"(r[0]), "=r"(r[1]), "=r"(r[2]), "=r"(r[3]) : "r"(addr));
}
__device__ __forceinline__ void mma16816(float* c, const uint32_t* a, const uint32_t* b) {
    asm volatile("mma.sync.aligned.m16n8k16.row.col.f32.f16.f16.f32 "
                 "{%0,%1,%2,%3},{%4,%5,%6,%7},{%8,%9},{%0,%1,%2,%3};"
                 : "+f"(c[0]), "+f"(c[1]), "+f"(c[2]), "+f"(c[3])
                 : "r"(a[0]), "r"(a[1]), "r"(a[2]), "r"(a[3]), "r"(b[0]), "r"(b[1]));
}

// ---------------------------------------------------------------------------
// Transpose x (B, N, T) -> fp16 xh at [(b*T+t)][n]
// ---------------------------------------------------------------------------
__global__ void transpose_half_x(const float* __restrict__ x,
                                 __half* __restrict__ xh) {
    __shared__ float tile[32][33];
    int b  = blockIdx.z;
    int t0 = blockIdx.x * 32;
    int n0 = blockIdx.y * 32;
    int tx = threadIdx.x, ty = threadIdx.y;   // 32 x 8
#pragma unroll
    for (int i = 0; i < 4; i++) {
        int n = n0 + ty + i * 8;
        int t = t0 + tx;
        if (t < T_STEPS)
            tile[ty + i * 8][tx] = x[((size_t)b * N_IN + n) * T_STEPS + t];
    }
    __syncthreads();
#pragma unroll
    for (int i = 0; i < 4; i++) {
        int t = t0 + ty + i * 8;
        int n = n0 + tx;
        if (t < T_STEPS)
            xh[((size_t)b * T_STEPS + t) * N_IN + n] =
                __float2half_rn(tile[tx][ty + i * 8]);
    }
}

// ---------------------------------------------------------------------------
// Convert W1 to fp16
// ---------------------------------------------------------------------------
__global__ void conv_w1(const float* __restrict__ w, __half* __restrict__ wh) {
    int i = blockIdx.x * 256 + threadIdx.x;
    wh[i] = __float2half_rn(w[i]);
}

// ---------------------------------------------------------------------------
// Transpose W2 (H2, H1) -> (H1, H2)
// ---------------------------------------------------------------------------
__global__ void transpose_w2_kernel(const float* __restrict__ w2,
                                    float* __restrict__ w2t) {
    __shared__ float tile[32][33];
    int k0 = blockIdx.x * 32;
    int j0 = blockIdx.y * 32;
    int tx = threadIdx.x, ty = threadIdx.y;
#pragma unroll
    for (int i = 0; i < 4; i++)
        tile[ty + i * 8][tx] = w2[(size_t)(j0 + ty + i * 8) * H1 + k0 + tx];
    __syncthreads();
#pragma unroll
    for (int i = 0; i < 4; i++)
        w2t[(size_t)(k0 + ty + i * 8) * H2 + j0 + tx] = tile[tx][ty + i * 8];
}

// ---------------------------------------------------------------------------
// GEMM1 via mma.sync fp16, single pass, fp16 output (R10 proven: 300 us):
//   h1[m][j] = fp16( sum_k x[m][k] * W1[j][k] + b1[j] )
// BM=128, BN=128, BK=64, 3-stage cp.async pipeline, ONE sync per k-chunk,
// 2 CTAs/SM.
// ---------------------------------------------------------------------------
#define BK        64
#define NKC       (N_IN / BK)        // 8
#define ROWB      144                // bytes per padded smem row (64h + 8h pad)
#define MATB      (128 * ROWB)       // 18432 bytes per matrix tile
#define STAGEB    (2 * MATB)         // A, W = 36864
#define NSTAGE    3
#define GEMM_SMEM (NSTAGE * STAGEB)  // 110592

__device__ __forceinline__ void g1_load_stage(uint32_t sbase, int kc,
                                              const __half* xh, const __half* wh,
                                              int m0, int j0, int tid) {
    int kb = kc * BK;
#pragma unroll
    for (int i = 0; i < 2; i++) {
        int c = tid + i * 256;              // 0..511: 128 rows x 4 segs
        int row = c >> 2, seg = c & 3;
        uint32_t d = (uint32_t)(row * ROWB + seg * 16);
        cp_async16(sbase + d,        xh + (size_t)(m0 + row) * N_IN + kb + seg * 8);
        cp_async16(sbase + MATB + d, wh + (size_t)(j0 + row) * N_IN + kb + seg * 8);
    }
    CP_COMMIT();
}

__global__ __launch_bounds__(256, 2) void gemm1_mma_kernel(
    const __half* __restrict__ xh, const __half* __restrict__ wh,
    const float* __restrict__ b1, __half* __restrict__ h1) {
    extern __shared__ char smem[];
    uint32_t sb = smem_u32(smem);
    int tid  = threadIdx.x;
    int wid  = tid >> 5, lane = tid & 31;
    int m0   = blockIdx.y * 128;
    int j0   = blockIdx.x * 128;
    int mbase = (wid & 1) * 64;          // 2 m-groups, warp tile 64 rows
    int nbase = (wid >> 1) * 32;         // 4 n-groups, warp tile 32 cols
    int grp  = lane >> 3, lrow = lane & 7;

    uint32_t aoff = (uint32_t)((mbase + (grp & 1) * 8 + lrow) * ROWB + (grp >> 1) * 16);
    uint32_t boff = (uint32_t)((nbase + (grp >> 1) * 8 + lrow) * ROWB + (grp & 1) * 16);

    float acc[4][4][4];
#pragma unroll
    for (int mt = 0; mt < 4; mt++)
#pragma unroll
        for (int nt = 0; nt < 4; nt++)
#pragma unroll
            for (int q = 0; q < 4; q++) acc[mt][nt][q] = 0.0f;

    // prologue: stages 0, 1
    g1_load_stage(sb,          0, xh, wh, m0, j0, tid);
    g1_load_stage(sb + STAGEB, 1, xh, wh, m0, j0, tid);

#pragma unroll 1
    for (int kc = 0; kc < NKC; kc++) {
        cp_wait<1>();      // stage kc landed (this thread's view)
        __syncthreads();   // publish kc to all + all warps done with kc-1
        if (kc + 2 < NKC)  // slot (kc+2)%3 == (kc-1)%3, freed by the sync above
            g1_load_stage(sb + ((kc + 2) % NSTAGE) * STAGEB, kc + 2,
                          xh, wh, m0, j0, tid);
        else
            CP_COMMIT();   // keep wait_group accounting in step

        uint32_t sA = sb + (kc % NSTAGE) * STAGEB;
        uint32_t sW = sA + MATB;
#pragma unroll
        for (int kk = 0; kk < 4; kk++) {
            uint32_t ah[4][4];
#pragma unroll
            for (int mt = 0; mt < 4; mt++)
                ldsm4(ah[mt], sA + aoff + mt * (16 * ROWB) + kk * 32);
            uint32_t bh[4][2];
#pragma unroll
            for (int nt2 = 0; nt2 < 2; nt2++) {
                uint32_t r[4];
                ldsm4t(r, sW + boff + nt2 * (16 * ROWB) + kk * 32);
                bh[nt2 * 2][0] = r[0]; bh[nt2 * 2][1] = r[1];
                bh[nt2 * 2 + 1][0] = r[2]; bh[nt2 * 2 + 1][1] = r[3];
            }
#pragma unroll
            for (int mt = 0; mt < 4; mt++)
#pragma unroll
                for (int nt = 0; nt < 4; nt++)
                    mma16816(acc[mt][nt], ah[mt], bh[nt]);
        }
    }

    // epilogue: add bias, store fp16
    int r0 = lane >> 2, c0 = (lane & 3) * 2;
#pragma unroll
    for (int nt = 0; nt < 4; nt++) {
        int col = j0 + nbase + nt * 8 + c0;
        float2 bb = *(const float2*)&b1[col];
#pragma unroll
        for (int mt = 0; mt < 4; mt++) {
            int row = m0 + mbase + mt * 16 + r0;
            __half2 v0 = __floats2half2_rn(acc[mt][nt][0] + bb.x, acc[mt][nt][1] + bb.y);
            __half2 v1 = __floats2half2_rn(acc[mt][nt][2] + bb.x, acc[mt][nt][3] + bb.y);
            *(__half2*)&h1[(size_t)row * H1 + col]       = v0;
            *(__half2*)&h1[(size_t)(row + 8) * H1 + col] = v1;
        }
    }
}

// ---------------------------------------------------------------------------
// Phase B (R9 proven config): RB=2 rows/block, 1024 blocks, 256 threads.
// Warp w: row = w>>2, quarter q = w&3, neurons k = q*128 + i*32 + lane (i<4).
// Double-buffered bitmasks -> 2 barriers/step. uint4 zero-skip word scan.
// ---------------------------------------------------------------------------
#define RB 2
__global__ __launch_bounds__(256) void phase_b_kernel(
    const __half* __restrict__ h1all, const float* __restrict__ w2t,
    const float* __restrict__ b2,    const float* __restrict__ Wo,
    const float* __restrict__ bo,    float* __restrict__ out) {
    __shared__ uint32_t s1bits[2][RB][16];
    __shared__ uint32_t s2bits[2][RB][8];
    __shared__ float    Wos[O_OUT * 256];
    __shared__ float    bos[8];

    int tid  = threadIdx.x;
    int wid  = tid >> 5, lane = tid & 31;
    int b0   = blockIdx.x * RB;
    int row  = wid >> 2;                 // 0..1
    int quar = wid & 3;                  // k-quarter

    for (int i = tid; i < O_OUT * 256; i += 256) Wos[i] = Wo[i];
    if (tid < O_OUT) bos[tid] = bo[tid];

    float v1[4];
#pragma unroll
    for (int i = 0; i < 4; i++) v1[i] = 0.0f;
    float v2[RB];
#pragma unroll
    for (int r = 0; r < RB; r++) v2[r] = 0.0f;
    float b2r = b2[tid];
    float vo = 0.0f, oac = 0.0f;         // LIF3: wid<2 = row, lanes 0..4 = cols

    const __half* hbase = h1all + ((size_t)(b0 + row) * T_STEPS) * H1
                                + quar * 128 + lane;
    // prefetch t=0
    __half cur[4], nxt[4];
#pragma unroll
    for (int i = 0; i < 4; i++) cur[i] = hbase[i * 32];
    __syncthreads();

#pragma unroll 1
    for (int t = 0; t < T_STEPS; t++) {
        int buf = t & 1;
        // issue next-t loads early (independent of everything below)
        if (t + 1 < T_STEPS) {
            const __half* hn = hbase + (size_t)(t + 1) * H1;
#pragma unroll
            for (int i = 0; i < 4; i++) nxt[i] = hn[i * 32];
        }

        // ---- LIF1 -> bitmask (word = quar*4+i, bit = lane) ----
#pragma unroll
        for (int i = 0; i < 4; i++) {
            float v = v1[i];
            v = v + (__half2float(cur[i]) - v) * 0.5f;
            bool sp = (v >= 1.0f);
            v1[i] = sp ? 0.0f : v;
            uint32_t m = __ballot_sync(0xffffffffu, sp);
            if (lane == 0) s1bits[buf][row][quar * 4 + i] = m;
        }
        __syncthreads();

        // ---- sparse GEMM2 + LIF2 (thread = col j = tid) ----
#pragma unroll
        for (int r = 0; r < RB; r++) {
            float acc = b2r;
            const uint4* wq = (const uint4*)s1bits[buf][r];
#pragma unroll
            for (int q = 0; q < 4; q++) {
                uint4 w4 = wq[q];
                if ((w4.x | w4.y | w4.z | w4.w) == 0u) continue;
                uint32_t ws[4] = {w4.x, w4.y, w4.z, w4.w};
#pragma unroll
                for (int c = 0; c < 4; c++) {
                    uint32_t word = ws[c];
                    while (word) {
                        int k = (q * 4 + c) * 32 + (__ffs(word) - 1);
                        word &= word - 1;
                        acc += w2t[(size_t)k * H2 + tid];
                    }
                }
            }
            float v = v2[r];
            v = v + (acc - v) * 0.5f;
            bool sp = (v >= 1.0f);
            v2[r] = sp ? 0.0f : v;
            uint32_t m = __ballot_sync(0xffffffffu, sp);
            if (lane == 0) s2bits[buf][r][wid] = m;
        }
        __syncthreads();

        // ---- sparse GEMM3 + LIF3 (wid<2 = row, lanes 0..4 = outputs) ----
        if (wid < RB && lane < O_OUT) {
            float sum = bos[lane];
#pragma unroll
            for (int w = 0; w < 8; w++) {
                uint32_t word = s2bits[buf][wid][w];
                while (word) {
                    int j = w * 32 + (__ffs(word) - 1);
                    word &= word - 1;
                    sum += Wos[lane * 256 + j];
                }
            }
            float v = vo;
            v = v + (sum - v) * 0.5f;
            bool sp = (v >= 1.0f);
            vo = sp ? 0.0f : v;
            if (sp) oac += 1.0f;
        }
        // no barrier: next step writes the OTHER buffer

#pragma unroll
        for (int i = 0; i < 4; i++) cur[i] = nxt[i];
    }

    if (wid < RB && lane < O_OUT)
        out[(size_t)(b0 + wid) * O_OUT + lane] = oac * (1.0f / T_STEPS);
}

// ---------------------------------------------------------------------------
extern "C" void kernel_launch(void* const* d_in, const int* in_sizes, int n_in,
                              void* d_out, int out_size) {
    const float* x  = (const float*)d_in[0];
    const float* W1 = (const float*)d_in[1];
    const float* b1 = (const float*)d_in[2];
    const float* W2 = (const float*)d_in[3];
    const float* b2 = (const float*)d_in[4];
    const float* Wo = (const float*)d_in[5];
    const float* bo = (const float*)d_in[6];
    float* out = (float*)d_out;

    __half *xh, *wh, *h1;
    float *w2t;
    cudaGetSymbolAddress((void**)&xh,  g_xh);
    cudaGetSymbolAddress((void**)&wh,  g_w1h);
    cudaGetSymbolAddress((void**)&h1,  g_h1);
    cudaGetSymbolAddress((void**)&w2t, g_w2t);

    cudaFuncSetAttribute(gemm1_mma_kernel,
                         cudaFuncAttributeMaxDynamicSharedMemorySize, GEMM_SMEM);

    transpose_half_x<<<dim3(4, 16, B_SZ), dim3(32, 8)>>>(x, xh);
    conv_w1<<<(H1 * N_IN) / 256, 256>>>(W1, wh);
    transpose_w2_kernel<<<dim3(16, 8), dim3(32, 8)>>>(W2, w2t);
    gemm1_mma_kernel<<<dim3(H1 / 128, M_TOT / 128), 256, GEMM_SMEM>>>(
        xh, wh, b1, h1);
    phase_b_kernel<<<B_SZ / RB, 256>>>(h1, w2t, b2, Wo, bo, out);
}

// round 13
// speedup vs baseline: 2.0985x; 1.0015x over previous
#include <cuda_runtime.h>
#include <cuda_fp16.h>
#include <cstdint>

#define B_SZ    2048
#define N_IN    512
#define T_STEPS 100
#define H1      512
#define H2      256
#define O_OUT   5
#define M_TOT   (B_SZ * T_STEPS)   // 204800

// ---------------- scratch globals (allocation-free rule) ----------------
__device__ __half g_xh[(size_t)M_TOT * N_IN];   // x transposed, fp16
__device__ __half g_w1h[H1 * N_IN];             // W1 fp16
__device__ __half g_h1[(size_t)M_TOT * H1];     // fp16 h1 for all t
__device__ float  g_w2t[H1 * H2];               // W2 transposed [k][j]

// ---------------- PTX helpers ----------------
__device__ __forceinline__ uint32_t smem_u32(const void* p) {
    uint32_t a;
    asm("{ .reg .u64 t; cvta.to.shared.u64 t, %1; cvt.u32.u64 %0, t; }"
        : "=r"(a) : "l"(p));
    return a;
}
__device__ __forceinline__ void cp_async16(uint32_t dst, const void* src) {
    asm volatile("cp.async.cg.shared.global [%0], [%1], 16;" :: "r"(dst), "l"(src));
}
#define CP_COMMIT() asm volatile("cp.async.commit_group;" ::: "memory")
template <int N>
__device__ __forceinline__ void cp_wait() {
    asm volatile("cp.async.wait_group %0;" :: "n"(N) : "memory");
}
__device__ __forceinline__ void ldsm4(uint32_t* r, uint32_t addr) {
    asm volatile("ldmatrix.sync.aligned.m8n8.x4.shared.b16 {%0,%1,%2,%3}, [%4];"
                 : "=r"(r[0]), "=r"(r[1]), "=r"(r[2]), "=r"(r[3]) : "r"(addr));
}
__device__ __forceinline__ void ldsm4t(uint32_t* r, uint32_t addr) {
    asm volatile("ldmatrix.sync.aligned.m8n8.x4.trans.shared.b16 {%0,%1,%2,%3}, [%4];"
                 : "=r"(r[0]), "=r"(r[1]), "=r"(r[2]), "=r"(r[3]) : "r"(addr));
}
__device__ __forceinline__ void mma16816(float* c, const uint32_t* a, const uint32_t* b) {
    asm volatile("mma.sync.aligned.m16n8k16.row.col.f32.f16.f16.f32 "
                 "{%0,%1,%2,%3},{%4,%5,%6,%7},{%8,%9},{%0,%1,%2,%3};"
                 : "+f"(c[0]), "+f"(c[1]), "+f"(c[2]), "+f"(c[3])
                 : "r"(a[0]), "r"(a[1]), "r"(a[2]), "r"(a[3]), "r"(b[0]), "r"(b[1]));
}

// ---------------------------------------------------------------------------
// Transpose x (B, N, T) -> fp16 xh at [(b*T+t)][n]
// ---------------------------------------------------------------------------
__global__ void transpose_half_x(const float* __restrict__ x,
                                 __half* __restrict__ xh) {
    __shared__ float tile[32][33];
    int b  = blockIdx.z;
    int t0 = blockIdx.x * 32;
    int n0 = blockIdx.y * 32;
    int tx = threadIdx.x, ty = threadIdx.y;   // 32 x 8
#pragma unroll
    for (int i = 0; i < 4; i++) {
        int n = n0 + ty + i * 8;
        int t = t0 + tx;
        if (t < T_STEPS)
            tile[ty + i * 8][tx] = x[((size_t)b * N_IN + n) * T_STEPS + t];
    }
    __syncthreads();
#pragma unroll
    for (int i = 0; i < 4; i++) {
        int t = t0 + ty + i * 8;
        int n = n0 + tx;
        if (t < T_STEPS)
            xh[((size_t)b * T_STEPS + t) * N_IN + n] =
                __float2half_rn(tile[tx][ty + i * 8]);
    }
}

// ---------------------------------------------------------------------------
// Convert W1 to fp16
// ---------------------------------------------------------------------------
__global__ void conv_w1(const float* __restrict__ w, __half* __restrict__ wh) {
    int i = blockIdx.x * 256 + threadIdx.x;
    wh[i] = __float2half_rn(w[i]);
}

// ---------------------------------------------------------------------------
// Transpose W2 (H2, H1) -> (H1, H2)
// ---------------------------------------------------------------------------
__global__ void transpose_w2_kernel(const float* __restrict__ w2,
                                    float* __restrict__ w2t) {
    __shared__ float tile[32][33];
    int k0 = blockIdx.x * 32;
    int j0 = blockIdx.y * 32;
    int tx = threadIdx.x, ty = threadIdx.y;
#pragma unroll
    for (int i = 0; i < 4; i++)
        tile[ty + i * 8][tx] = w2[(size_t)(j0 + ty + i * 8) * H1 + k0 + tx];
    __syncthreads();
#pragma unroll
    for (int i = 0; i < 4; i++)
        w2t[(size_t)(k0 + ty + i * 8) * H2 + j0 + tx] = tile[tx][ty + i * 8];
}

// ---------------------------------------------------------------------------
// GEMM1 via mma.sync fp16, single pass, fp16 output:
//   h1[m][j] = fp16( sum_k x[m][k] * W1[j][k] + b1[j] )
// BM=128, BN=128, BK=64, 3-stage cp.async pipeline.
// R9's PROVEN two-sync loop skeleton (sync; load; wait<2>; sync; compute),
// only BK changed 32->64 (barriers per CTA: 32 -> 16). 2 CTAs/SM.
// ---------------------------------------------------------------------------
#define BK        64
#define NKC       (N_IN / BK)        // 8
#define ROWB      144                // bytes per padded smem row (64h + 8h pad)
#define MATB      (128 * ROWB)       // 18432 bytes per matrix tile
#define STAGEB    (2 * MATB)         // A, W = 36864
#define NSTAGE    3
#define GEMM_SMEM (NSTAGE * STAGEB)  // 110592

__device__ __forceinline__ void g1_load_stage(uint32_t sbase, int kc,
                                              const __half* xh, const __half* wh,
                                              int m0, int j0, int tid) {
    int kb = kc * BK;
#pragma unroll
    for (int i = 0; i < 2; i++) {
        int c = tid + i * 256;              // 0..511: 128 rows x 4 segs
        int row = c >> 2, seg = c & 3;
        uint32_t d = (uint32_t)(row * ROWB + seg * 16);
        cp_async16(sbase + d,        xh + (size_t)(m0 + row) * N_IN + kb + seg * 8);
        cp_async16(sbase + MATB + d, wh + (size_t)(j0 + row) * N_IN + kb + seg * 8);
    }
    CP_COMMIT();
}

__global__ __launch_bounds__(256, 2) void gemm1_mma_kernel(
    const __half* __restrict__ xh, const __half* __restrict__ wh,
    const float* __restrict__ b1, __half* __restrict__ h1) {
    extern __shared__ char smem[];
    uint32_t sb = smem_u32(smem);
    int tid  = threadIdx.x;
    int wid  = tid >> 5, lane = tid & 31;
    int m0   = blockIdx.y * 128;
    int j0   = blockIdx.x * 128;
    int mbase = (wid & 1) * 64;          // 2 m-groups, warp tile 64 rows
    int nbase = (wid >> 1) * 32;         // 4 n-groups, warp tile 32 cols
    int grp  = lane >> 3, lrow = lane & 7;

    uint32_t aoff = (uint32_t)((mbase + (grp & 1) * 8 + lrow) * ROWB + (grp >> 1) * 16);
    uint32_t boff = (uint32_t)((nbase + (grp >> 1) * 8 + lrow) * ROWB + (grp & 1) * 16);

    float acc[4][4][4];
#pragma unroll
    for (int mt = 0; mt < 4; mt++)
#pragma unroll
        for (int nt = 0; nt < 4; nt++)
#pragma unroll
            for (int q = 0; q < 4; q++) acc[mt][nt][q] = 0.0f;

    // prologue: stages 0, 1
    g1_load_stage(sb,          0, xh, wh, m0, j0, tid);
    g1_load_stage(sb + STAGEB, 1, xh, wh, m0, j0, tid);

#pragma unroll 1
    for (int kc = 0; kc < NKC; kc++) {
        __syncthreads();   // all warps done with buffer (kc+2)%3's old data
        if (kc + 2 < NKC)
            g1_load_stage(sb + ((kc + 2) % NSTAGE) * STAGEB, kc + 2,
                          xh, wh, m0, j0, tid);
        else
            CP_COMMIT();   // keep wait_group accounting in step
        cp_wait<2>();      // stage kc's group has landed
        __syncthreads();

        uint32_t sA = sb + (kc % NSTAGE) * STAGEB;
        uint32_t sW = sA + MATB;
#pragma unroll
        for (int kk = 0; kk < 4; kk++) {
            uint32_t ah[4][4];
#pragma unroll
            for (int mt = 0; mt < 4; mt++)
                ldsm4(ah[mt], sA + aoff + mt * (16 * ROWB) + kk * 32);
            uint32_t bh[4][2];
#pragma unroll
            for (int nt2 = 0; nt2 < 2; nt2++) {
                uint32_t r[4];
                ldsm4t(r, sW + boff + nt2 * (16 * ROWB) + kk * 32);
                bh[nt2 * 2][0] = r[0]; bh[nt2 * 2][1] = r[1];
                bh[nt2 * 2 + 1][0] = r[2]; bh[nt2 * 2 + 1][1] = r[3];
            }
#pragma unroll
            for (int mt = 0; mt < 4; mt++)
#pragma unroll
                for (int nt = 0; nt < 4; nt++)
                    mma16816(acc[mt][nt], ah[mt], bh[nt]);
        }
    }

    // epilogue: add bias, store fp16
    int r0 = lane >> 2, c0 = (lane & 3) * 2;
#pragma unroll
    for (int nt = 0; nt < 4; nt++) {
        int col = j0 + nbase + nt * 8 + c0;
        float2 bb = *(const float2*)&b1[col];
#pragma unroll
        for (int mt = 0; mt < 4; mt++) {
            int row = m0 + mbase + mt * 16 + r0;
            __half2 v0 = __floats2half2_rn(acc[mt][nt][0] + bb.x, acc[mt][nt][1] + bb.y);
            __half2 v1 = __floats2half2_rn(acc[mt][nt][2] + bb.x, acc[mt][nt][3] + bb.y);
            *(__half2*)&h1[(size_t)row * H1 + col]       = v0;
            *(__half2*)&h1[(size_t)(row + 8) * H1 + col] = v1;
        }
    }
}

// ---------------------------------------------------------------------------
// Phase B (R9 proven config, byte-identical): RB=2 rows/block, 1024 blocks.
// Warp w: row = w>>2, quarter q = w&3, neurons k = q*128 + i*32 + lane (i<4).
// Double-buffered bitmasks -> 2 barriers/step. uint4 zero-skip word scan.
// ---------------------------------------------------------------------------
#define RB 2
__global__ __launch_bounds__(256) void phase_b_kernel(
    const __half* __restrict__ h1all, const float* __restrict__ w2t,
    const float* __restrict__ b2,    const float* __restrict__ Wo,
    const float* __restrict__ bo,    float* __restrict__ out) {
    __shared__ uint32_t s1bits[2][RB][16];
    __shared__ uint32_t s2bits[2][RB][8];
    __shared__ float    Wos[O_OUT * 256];
    __shared__ float    bos[8];

    int tid  = threadIdx.x;
    int wid  = tid >> 5, lane = tid & 31;
    int b0   = blockIdx.x * RB;
    int row  = wid >> 2;                 // 0..1
    int quar = wid & 3;                  // k-quarter

    for (int i = tid; i < O_OUT * 256; i += 256) Wos[i] = Wo[i];
    if (tid < O_OUT) bos[tid] = bo[tid];

    float v1[4];
#pragma unroll
    for (int i = 0; i < 4; i++) v1[i] = 0.0f;
    float v2[RB];
#pragma unroll
    for (int r = 0; r < RB; r++) v2[r] = 0.0f;
    float b2r = b2[tid];
    float vo = 0.0f, oac = 0.0f;         // LIF3: wid<2 = row, lanes 0..4 = cols

    const __half* hbase = h1all + ((size_t)(b0 + row) * T_STEPS) * H1
                                + quar * 128 + lane;
    // prefetch t=0
    __half cur[4], nxt[4];
#pragma unroll
    for (int i = 0; i < 4; i++) cur[i] = hbase[i * 32];
    __syncthreads();

#pragma unroll 1
    for (int t = 0; t < T_STEPS; t++) {
        int buf = t & 1;
        // issue next-t loads early (independent of everything below)
        if (t + 1 < T_STEPS) {
            const __half* hn = hbase + (size_t)(t + 1) * H1;
#pragma unroll
            for (int i = 0; i < 4; i++) nxt[i] = hn[i * 32];
        }

        // ---- LIF1 -> bitmask (word = quar*4+i, bit = lane) ----
#pragma unroll
        for (int i = 0; i < 4; i++) {
            float v = v1[i];
            v = v + (__half2float(cur[i]) - v) * 0.5f;
            bool sp = (v >= 1.0f);
            v1[i] = sp ? 0.0f : v;
            uint32_t m = __ballot_sync(0xffffffffu, sp);
            if (lane == 0) s1bits[buf][row][quar * 4 + i] = m;
        }
        __syncthreads();

        // ---- sparse GEMM2 + LIF2 (thread = col j = tid) ----
#pragma unroll
        for (int r = 0; r < RB; r++) {
            float acc = b2r;
            const uint4* wq = (const uint4*)s1bits[buf][r];
#pragma unroll
            for (int q = 0; q < 4; q++) {
                uint4 w4 = wq[q];
                if ((w4.x | w4.y | w4.z | w4.w) == 0u) continue;
                uint32_t ws[4] = {w4.x, w4.y, w4.z, w4.w};
#pragma unroll
                for (int c = 0; c < 4; c++) {
                    uint32_t word = ws[c];
                    while (word) {
                        int k = (q * 4 + c) * 32 + (__ffs(word) - 1);
                        word &= word - 1;
                        acc += w2t[(size_t)k * H2 + tid];
                    }
                }
            }
            float v = v2[r];
            v = v + (acc - v) * 0.5f;
            bool sp = (v >= 1.0f);
            v2[r] = sp ? 0.0f : v;
            uint32_t m = __ballot_sync(0xffffffffu, sp);
            if (lane == 0) s2bits[buf][r][wid] = m;
        }
        __syncthreads();

        // ---- sparse GEMM3 + LIF3 (wid<2 = row, lanes 0..4 = outputs) ----
        if (wid < RB && lane < O_OUT) {
            float sum = bos[lane];
#pragma unroll
            for (int w = 0; w < 8; w++) {
                uint32_t word = s2bits[buf][wid][w];
                while (word) {
                    int j = w * 32 + (__ffs(word) - 1);
                    word &= word - 1;
                    sum += Wos[lane * 256 + j];
                }
            }
            float v = vo;
            v = v + (sum - v) * 0.5f;
            bool sp = (v >= 1.0f);
            vo = sp ? 0.0f : v;
            if (sp) oac += 1.0f;
        }
        // no barrier: next step writes the OTHER buffer

#pragma unroll
        for (int i = 0; i < 4; i++) cur[i] = nxt[i];
    }

    if (wid < RB && lane < O_OUT)
        out[(size_t)(b0 + wid) * O_OUT + lane] = oac * (1.0f / T_STEPS);
}

// ---------------------------------------------------------------------------
extern "C" void kernel_launch(void* const* d_in, const int* in_sizes, int n_in,
                              void* d_out, int out_size) {
    const float* x  = (const float*)d_in[0];
    const float* W1 = (const float*)d_in[1];
    const float* b1 = (const float*)d_in[2];
    const float* W2 = (const float*)d_in[3];
    const float* b2 = (const float*)d_in[4];
    const float* Wo = (const float*)d_in[5];
    const float* bo = (const float*)d_in[6];
    float* out = (float*)d_out;

    __half *xh, *wh, *h1;
    float *w2t;
    cudaGetSymbolAddress((void**)&xh,  g_xh);
    cudaGetSymbolAddress((void**)&wh,  g_w1h);
    cudaGetSymbolAddress((void**)&h1,  g_h1);
    cudaGetSymbolAddress((void**)&w2t, g_w2t);

    cudaFuncSetAttribute(gemm1_mma_kernel,
                         cudaFuncAttributeMaxDynamicSharedMemorySize, GEMM_SMEM);

    transpose_half_x<<<dim3(4, 16, B_SZ), dim3(32, 8)>>>(x, xh);
    conv_w1<<<(H1 * N_IN) / 256, 256>>>(W1, wh);
    transpose_w2_kernel<<<dim3(16, 8), dim3(32, 8)>>>(W2, w2t);
    gemm1_mma_kernel<<<dim3(H1 / 128, M_TOT / 128), 256, GEMM_SMEM>>>(
        xh, wh, b1, h1);
    phase_b_kernel<<<B_SZ / RB, 256>>>(h1, w2t, b2, Wo, bo, out);
}